// round 16
// baseline (speedup 1.0000x reference)
#include <cuda_runtime.h>
#include <cuda_fp16.h>
#include <math.h>
#include <stdint.h>

#define BSZ   64
#define SEQ   1024
#define IND   512
#define EMB   1024
#define HID   512
#define KSEL  306
#define MR    (BSZ*KSEL)     /* 19584 = 153*128 */
#define MT    153            /* m-tiles */
#define KB2   1024           /* GEMM-B K dim */

// ---------------- scratch (device globals: no allocation allowed) -----------
__device__ int   g_len[BSZ];
__device__ int   g_plen[BSZ];
__device__ float g_sps[BSZ*4*SEQ];             /* row-quarter partial exp sums */
__device__ int   g_topk[BSZ*KSEL];
__device__ __half g_XA[(size_t)MR*KB2];        /* [X | A2] packed, stride 1024 */
__device__ __half g_W1h[(size_t)HID*IND];      /* w1^T, stride 512 */
__device__ __half g_Wb[(size_t)EMB*KB2];       /* [lin_w^T | w2^T], stride 1024 */
__device__ __half g_Hh[(size_t)MR*HID];        /* GEMM-A output (pre-BN), fp16 */
__device__ float g_psum[2*MT*HID];
__device__ float g_psq [2*MT*HID];
__device__ float g_scale[HID];
__device__ float g_shift[HID];
__device__ float g_pmax[(size_t)2*MT*EMB];

// ---------------- small PTX helpers -----------------------------------------
__device__ __forceinline__ uint32_t smem_to_u32(const void* p) {
    uint32_t a;
    asm("{ .reg .u64 t; cvta.to.shared.u64 t, %1; cvt.u32.u64 %0, t; }" : "=r"(a) : "l"(p));
    return a;
}
__device__ __forceinline__ void cp_async16(uint32_t saddr, const void* gaddr) {
    asm volatile("cp.async.cg.shared.global [%0], [%1], 16;" :: "r"(saddr), "l"(gaddr));
}
#define CP_COMMIT() asm volatile("cp.async.commit_group;" ::: "memory")
#define CP_WAIT(N)  asm volatile("cp.async.wait_group %0;" :: "n"(N) : "memory")

__device__ __forceinline__ void ldm_x4(uint32_t& r0, uint32_t& r1, uint32_t& r2, uint32_t& r3,
                                       uint32_t addr) {
    asm volatile("ldmatrix.sync.aligned.m8n8.x4.shared.b16 {%0,%1,%2,%3}, [%4];"
                 : "=r"(r0), "=r"(r1), "=r"(r2), "=r"(r3) : "r"(addr));
}
__device__ __forceinline__ void mma16816(float* c, uint32_t a0, uint32_t a1, uint32_t a2,
                                         uint32_t a3, uint32_t b0, uint32_t b1) {
    asm volatile("mma.sync.aligned.m16n8k16.row.col.f32.f16.f16.f32 "
                 "{%0,%1,%2,%3}, {%4,%5,%6,%7}, {%8,%9}, {%0,%1,%2,%3};"
                 : "+f"(c[0]), "+f"(c[1]), "+f"(c[2]), "+f"(c[3])
                 : "r"(a0), "r"(a1), "r"(a2), "r"(a3), "r"(b0), "r"(b1));
}

// fast exp on FMA pipe: exp(x) = 2^(x*log2e)
__device__ __forceinline__ float fexp(float x) {
    float t  = x * 1.44269504088896341f;
    float fi = rintf(t);
    float f  = t - fi;
    float p  = 1.54035303934e-4f;
    p = fmaf(p, f, 1.33335581464e-3f);
    p = fmaf(p, f, 9.61812910763e-3f);
    p = fmaf(p, f, 5.55041086648e-2f);
    p = fmaf(p, f, 2.40226506959e-1f);
    p = fmaf(p, f, 6.93147180560e-1f);
    p = fmaf(p, f, 1.0f);
    return p * __int_as_float(((int)fi + 127) << 23);
}
__device__ __forceinline__ float nfix(float x) {
    if (!isfinite(x)) x = 0.0f;
    return fminf(fmaxf(x, -60.0f), 60.0f);
}

// ---------------- K0: token lengths (1024 thr, __syncthreads_count) ---------
__global__ void k_lens(const int* w32) {
    int b = blockIdx.x;
    int t = threadIdx.x;
    int podd = (t < 512) ? (w32[2 * t + 1] != 0) : 0;
    int odd_nz = __syncthreads_count(podd);
    int is64 = (odd_nz == 0);
    int nz;
    if (is64) {
        size_t o = 2 * ((size_t)b * SEQ + t);
        nz = ((w32[o] | w32[o + 1]) != 0);
    } else {
        nz = (w32[(size_t)b * SEQ + t] != 0);
    }
    int cnt = __syncthreads_count(nz);
    if (t == 0) {
        int tl = max(cnt, 1);
        g_len[b] = tl;
        g_plen[b] = min(max(tl - 2, 1), KSEL);
    }
}

// ---------------- K1: partial exp-sums over row quarters (2 cols/thread) ----
__global__ void k_scorep(const float* __restrict__ atten) {
    int b    = blockIdx.z;
    int q    = blockIdx.y;                      // row quarter
    int col0 = (blockIdx.x * 256 + threadIdx.x) * 2;
    int len  = g_len[b];
    float sa = 0.0f, sb = 0.0f;
    if (col0 + 1 < len) {                       // both cols active (common case)
        const float* base = atten + (size_t)b * SEQ * SEQ + (size_t)q * 256 * SEQ + col0;
        float a0 = 0, a1 = 0, a2 = 0, a3 = 0;
        float b0 = 0, b1 = 0, b2 = 0, b3 = 0;
#pragma unroll 2
        for (int r = 0; r < 256; r += 4) {
            float2 x0 = *(const float2*)(base + (size_t)(r + 0) * SEQ);
            float2 x1 = *(const float2*)(base + (size_t)(r + 1) * SEQ);
            float2 x2 = *(const float2*)(base + (size_t)(r + 2) * SEQ);
            float2 x3 = *(const float2*)(base + (size_t)(r + 3) * SEQ);
            a0 += fexp(nfix(x0.x)); b0 += fexp(nfix(x0.y));
            a1 += fexp(nfix(x1.x)); b1 += fexp(nfix(x1.y));
            a2 += fexp(nfix(x2.x)); b2 += fexp(nfix(x2.y));
            a3 += fexp(nfix(x3.x)); b3 += fexp(nfix(x3.y));
        }
        sa = (a0 + a1) + (a2 + a3);
        sb = (b0 + b1) + (b2 + b3);
    } else if (col0 > 0 && col0 < len) {        // edge: only first col active
        const float* base = atten + (size_t)b * SEQ * SEQ + (size_t)q * 256 * SEQ + col0;
        float a0 = 0, a1 = 0, a2 = 0, a3 = 0;
#pragma unroll 2
        for (int r = 0; r < 256; r += 4) {
            a0 += fexp(nfix(base[(size_t)(r + 0) * SEQ]));
            a1 += fexp(nfix(base[(size_t)(r + 1) * SEQ]));
            a2 += fexp(nfix(base[(size_t)(r + 2) * SEQ]));
            a3 += fexp(nfix(base[(size_t)(r + 3) * SEQ]));
        }
        sa = (a0 + a1) + (a2 + a3);
    }
    float* dst = g_sps + ((size_t)b * 4 + q) * SEQ + col0;
    dst[0] = sa;
    dst[1] = sb;
}

// ---------------- K2b: fused scoref + top-K sort (blocks<64) | w1^T (rest) --
__global__ void __launch_bounds__(1024) k_topk_prepw(const float* __restrict__ w1,
                                                     const float* __restrict__ atten) {
    __shared__ unsigned long long key[SEQ];       // 8 KB
    __shared__ float ts[4][32][33];               // transpose wing
    int tid = threadIdx.x;  // 1024
    if (blockIdx.x < BSZ) {
        int b = blockIdx.x;
        int len = g_len[b];
        int eos = len - 1;
        float out;
        if (tid >= len) {
            out = 0.0f;
        } else if (tid == 0 || tid == eos) {
            out = 1.0f / 1024.0f;
        } else {
            const float* sp = g_sps + (size_t)b * 4 * SEQ + tid;
            float s = (sp[0] + sp[SEQ]) + (sp[2 * SEQ] + sp[3 * SEQ]);
            float aeos = nfix(atten[(size_t)b * SEQ * SEQ + (size_t)eos * SEQ + tid]);
            out = fexp(aeos) / s;
        }
        unsigned int vb = __float_as_uint(out);
        key[tid] = ((unsigned long long)vb << 32) | (unsigned int)(SEQ - 1 - tid);
        __syncthreads();
        for (int k = 2; k <= SEQ; k <<= 1) {
            for (int j = k >> 1; j > 0; j >>= 1) {
                int i = tid, ixj = i ^ j;
                if (ixj > i) {
                    bool desc = ((i & k) == 0);
                    unsigned long long a = key[i], c = key[ixj];
                    if (desc ? (a < c) : (a > c)) { key[i] = c; key[ixj] = a; }
                }
                __syncthreads();
            }
        }
        if (tid < KSEL)
            g_topk[b * KSEL + tid] = (SEQ - 1) - (int)(key[tid] & 0xFFFFFFFFu);
    } else {
        int idx = blockIdx.x - BSZ;               // 0..63
        int g  = tid >> 8;                        // tile-in-block 0..3
        int t  = tid & 255;
        int tx = t & 31, ty = t >> 5;             // (32,8)
        int n0 = (idx & 15) * 32;
        int k0 = (idx >> 4) * 128 + g * 32;
#pragma unroll
        for (int i = 0; i < 4; i++) {
            int kl = ty + i * 8;
            ts[g][kl][tx] = w1[(size_t)(k0 + kl) * HID + n0 + tx];
        }
        __syncthreads();
#pragma unroll
        for (int i = 0; i < 4; i++) {
            int nl = ty + i * 8;
            g_W1h[(size_t)(n0 + nl) * IND + k0 + tx] =
                __float2half_rn(ts[g][tx][nl]);
        }
    }
}

// ---------------- K3: gather, warp-per-row (MLP=4, no block sync) ------------
__global__ void __launch_bounds__(256) k_gather(const float* __restrict__ feats) {
    int warp = (blockIdx.x * 8) + (threadIdx.x >> 5);   // row index
    if (warp >= MR) return;
    int lane = threadIdx.x & 31;
    int b   = warp / KSEL;
    int idx = g_topk[warp];
    const float4* src = (const float4*)(feats + ((size_t)b * SEQ + idx) * IND);
    float4 v0 = src[lane];
    float4 v1 = src[lane + 32];
    float4 v2 = src[lane + 64];
    float4 v3 = src[lane + 96];
    float ss = v0.x*v0.x + v0.y*v0.y + v0.z*v0.z + v0.w*v0.w
             + v1.x*v1.x + v1.y*v1.y + v1.z*v1.z + v1.w*v1.w
             + v2.x*v2.x + v2.y*v2.y + v2.z*v2.z + v2.w*v2.w
             + v3.x*v3.x + v3.y*v3.y + v3.z*v3.z + v3.w*v3.w;
#pragma unroll
    for (int o = 16; o > 0; o >>= 1) ss += __shfl_xor_sync(0xffffffffu, ss, o);
    float sc = 1.0f / fmaxf(sqrtf(ss), 1e-6f);
    __half* dst = g_XA + (size_t)warp * KB2;
    union { __half h4[4]; uint2 u; } H;
    float4 vv[4] = {v0, v1, v2, v3};
#pragma unroll
    for (int i = 0; i < 4; i++) {
        H.h4[0] = __float2half_rn(vv[i].x * sc);
        H.h4[1] = __float2half_rn(vv[i].y * sc);
        H.h4[2] = __float2half_rn(vv[i].z * sc);
        H.h4[3] = __float2half_rn(vv[i].w * sc);
        *(uint2*)(dst + (lane + i * 32) * 4) = H.u;
    }
}

// ---------------- K3b: Wb transpose (yoff selects lin_w / w2 half) ----------
__global__ void k_prepwb(const float* __restrict__ W, int koff) {
    __shared__ float s[32][33];
    int n0 = blockIdx.x * 32;
    int k0 = blockIdx.y * 32;
    int tx = threadIdx.x, ty = threadIdx.y;   // (32,8)
#pragma unroll
    for (int i = 0; i < 4; i++) {
        int kl = ty + i * 8;
        s[kl][tx] = W[(size_t)(k0 + kl) * EMB + n0 + tx];
    }
    __syncthreads();
#pragma unroll
    for (int i = 0; i < 4; i++) {
        int nl = ty + i * 8;
        g_Wb[(size_t)(n0 + nl) * KB2 + koff + k0 + tx] = __float2half_rn(s[tx][nl]);
    }
}

// ---------------- fp16 HMMA GEMM (128x128 tile, BK=64, 3-stage, full unroll) -
#define SKROW 144                /* 64 fp16 = 128 B + 16 pad (ldmatrix conflict-free) */
#define TILEB (128*SKROW)        /* 18432 B */
#define STAGEB (2*TILEB)         /* 36864 B */
#define GSMEM (3*STAGEB)         /* 110592 B, 3 stages */
#define FBS 132                  /* epilogue float buffer row stride */

template <int MODE, int LDA, int LDB, int KTILES>
__global__ void __launch_bounds__(256, 2) k_mmagemm(
    const __half* __restrict__ Ah, const __half* __restrict__ Bh,
    const float* __restrict__ bias0, const float* __restrict__ bias1)
{
    extern __shared__ char smem[];
    const uint32_t sb = smem_to_u32(smem);
    const int tid = threadIdx.x;
    const int lane = tid & 31;
    const int wid  = tid >> 5;
    const int warp_m = wid & 1;        // 2 warps in M
    const int warp_n = wid >> 1;       // 4 warps in N
    const int m0 = blockIdx.y * 128;
    const int n0 = blockIdx.x * 128;

    const int lrow = tid >> 3;         // 0..31
    const int lch  = tid & 7;          // 16B chunk within 128B row

    const __half* gA = Ah + (size_t)(m0 + lrow) * LDA + lch * 8;
    const __half* gB = Bh + (size_t)(n0 + lrow) * LDB + lch * 8;
    const uint32_t sA = sb + lrow * SKROW + lch * 16;
    const uint32_t sB = sb + TILEB + lrow * SKROW + lch * 16;

    auto stage_load = [&](int st, int kt) {
        const uint32_t so = (uint32_t)st * STAGEB;
        const int ko = kt * 64;
#pragma unroll
        for (int it = 0; it < 4; it++) {
            cp_async16(sA + so + it * 32 * SKROW, gA + (size_t)(it * 32) * LDA + ko);
            cp_async16(sB + so + it * 32 * SKROW, gB + (size_t)(it * 32) * LDB + ko);
        }
    };

    stage_load(0, 0); CP_COMMIT();
    stage_load(1, 1); CP_COMMIT();

    float acc[4][4][4];
#pragma unroll
    for (int i = 0; i < 4; i++)
#pragma unroll
        for (int j = 0; j < 4; j++)
#pragma unroll
            for (int c = 0; c < 4; c++) acc[i][j][c] = 0.0f;

    const int lr16 = lane & 15;
    const int lkh  = (lane >> 4) * 16;   // byte offset for k-half
    const uint32_t aAh0 = sb + (warp_m * 64 + lr16) * SKROW + lkh;
    const uint32_t aBh0 = sb + TILEB + (warp_n * 32 + lr16) * SKROW + lkh;

#pragma unroll
    for (int kt = 0; kt < KTILES; kt++) {
        if (kt + 2 < KTILES) {
            CP_WAIT(1);
            __syncthreads();
            stage_load((kt + 2) % 3, kt + 2); CP_COMMIT();
        } else {
            CP_WAIT(0);
            __syncthreads();
        }

        const uint32_t so = (uint32_t)(kt % 3) * STAGEB;   // compile-time after unroll
        const uint32_t aAh = aAh0 + so;
        const uint32_t aBh = aBh0 + so;
#pragma unroll
        for (int kk = 0; kk < 4; kk++) {
            const uint32_t kb = kk * 32;
            uint32_t bh[4][2];
            {
                uint32_t r0, r1, r2, r3;
                ldm_x4(r0, r1, r2, r3, aBh + kb);
                bh[0][0] = r0; bh[0][1] = r2; bh[1][0] = r1; bh[1][1] = r3;
                ldm_x4(r0, r1, r2, r3, aBh + 16 * SKROW + kb);
                bh[2][0] = r0; bh[2][1] = r2; bh[3][0] = r1; bh[3][1] = r3;
            }
#pragma unroll
            for (int mi = 0; mi < 4; mi++) {
                uint32_t a0, a1, a2, a3;
                ldm_x4(a0, a1, a2, a3, aAh + mi * 16 * SKROW + kb);
#pragma unroll
                for (int nj = 0; nj < 4; nj++)
                    mma16816(acc[mi][nj], a0, a1, a2, a3, bh[nj][0], bh[nj][1]);
            }
        }
    }

    // ---------------- epilogue ----------------
    const int rg = lane >> 2;            // row in 8-group
    const int cg = (lane & 3) * 2;       // col pair

    if (MODE == 0) {
        float s[4][2] = {{0,0},{0,0},{0,0},{0,0}};
        float q[4][2] = {{0,0},{0,0},{0,0},{0,0}};
#pragma unroll
        for (int mi = 0; mi < 4; mi++) {
#pragma unroll
            for (int nj = 0; nj < 4; nj++) {
                int m = m0 + warp_m * 64 + mi * 16 + rg;
                int n = n0 + warp_n * 32 + nj * 8 + cg;
                float* c = acc[mi][nj];
                float bv0 = bias0[n];
                float bv1 = bias0[n + 1];
                float2 v01 = make_float2(c[0] + bv0, c[1] + bv1);
                float2 v23 = make_float2(c[2] + bv0, c[3] + bv1);
                *(__half2*)(g_Hh + (size_t)m * HID + n) =
                    __floats2half2_rn(v01.x, v01.y);
                *(__half2*)(g_Hh + (size_t)(m + 8) * HID + n) =
                    __floats2half2_rn(v23.x, v23.y);
                s[nj][0] += v01.x + v23.x;  s[nj][1] += v01.y + v23.y;
                q[nj][0] += v01.x * v01.x + v23.x * v23.x;
                q[nj][1] += v01.y * v01.y + v23.y * v23.y;
            }
        }
#pragma unroll
        for (int o = 4; o <= 16; o <<= 1)
#pragma unroll
            for (int nj = 0; nj < 4; nj++)
#pragma unroll
                for (int p = 0; p < 2; p++) {
                    s[nj][p] += __shfl_xor_sync(0xffffffffu, s[nj][p], o);
                    q[nj][p] += __shfl_xor_sync(0xffffffffu, q[nj][p], o);
                }
        if (rg == 0) {
            int part = blockIdx.y * 2 + warp_m;
            int cbase = n0 + warp_n * 32;
#pragma unroll
            for (int nj = 0; nj < 4; nj++)
#pragma unroll
                for (int p = 0; p < 2; p++) {
                    int cc = cbase + nj * 8 + cg + p;
                    g_psum[part * HID + cc] = s[nj][p];
                    g_psq [part * HID + cc] = q[nj][p];
                }
        }
    } else {
        __syncthreads();                 // all smem reads done; reuse as float buf
        float* fb = (float*)smem;        // 128 x FBS floats
        float* cb = fb + 128 * FBS;      // 4 x 128 combine buffer
#pragma unroll
        for (int mi = 0; mi < 4; mi++) {
#pragma unroll
            for (int nj = 0; nj < 4; nj++) {
                int mrow = warp_m * 64 + mi * 16 + rg;
                int nloc = warp_n * 32 + nj * 8 + cg;
                int n = n0 + nloc;
                float* c = acc[mi][nj];
                float2 b0 = *(const float2*)(bias0 + n);
                float2 b1 = *(const float2*)(bias1 + n);
                float bx = b0.x + b1.x, by = b0.y + b1.y;
                fb[mrow * FBS + nloc]           = c[0] + bx;
                fb[mrow * FBS + nloc + 1]       = c[1] + by;
                fb[(mrow + 8) * FBS + nloc]     = c[2] + bx;
                fb[(mrow + 8) * FBS + nloc + 1] = c[3] + by;
            }
        }
        __syncthreads();
        int col  = tid & 127;
        int half = tid >> 7;
        int b0i  = m0 / KSEL;
        int off0 = m0 - b0i * KSEL;
        int split = min(max((b0i + 1) * KSEL - m0, 0), 128);
        int pl0 = g_plen[b0i];
        int pl1 = (b0i + 1 < BSZ) ? g_plen[b0i + 1] : 0;
        int end0 = min(split, pl0 - off0);
        int end1 = min(128, split + pl1);
        float mx0 = -INFINITY, mx1 = -INFINITY;
        int rbeg = half * 64;
#pragma unroll 4
        for (int r = rbeg; r < rbeg + 64; r++) {
            float v = fb[r * FBS + col];
            if (r < end0) mx0 = fmaxf(mx0, v);
            else if (r >= split && r < end1) mx1 = fmaxf(mx1, v);
        }
        cb[(half * 2 + 0) * 128 + col] = mx0;
        cb[(half * 2 + 1) * 128 + col] = mx1;
        __syncthreads();
        if (tid < 128) {
            float a0 = fmaxf(cb[0 * 128 + tid], cb[2 * 128 + tid]);
            float a1 = fmaxf(cb[1 * 128 + tid], cb[3 * 128 + tid]);
            g_pmax[(size_t)(blockIdx.y * 2 + 0) * EMB + n0 + tid] = a0;
            g_pmax[(size_t)(blockIdx.y * 2 + 1) * EMB + n0 + tid] = a1;
        }
    }
}

// ---------------- K5b: BN finalize -------------------------------------------
__global__ void k_bnfin(const float* __restrict__ g1, const float* __restrict__ be1) {
    int c = blockIdx.x * 256 + threadIdx.x;   // 512 cols
    float s = 0, q = 0;
    for (int p = 0; p < 2 * MT; p++) { s += g_psum[p * HID + c]; q += g_psq[p * HID + c]; }
    const float invN = 1.0f / (float)MR;
    float mu  = s * invN;
    float var = q * invN - mu * mu;
    float inv = 1.0f / sqrtf(var + 1e-5f);
    float sc  = g1[c] * inv;
    g_scale[c] = sc;
    g_shift[c] = be1[c] - mu * sc;
}

// ---------------- K5c: A2 = relu(BN(h)) -> fp16 into g_XA[:,512:1024] --------
__global__ void k_act() {
    int row = blockIdx.x;            // MR blocks, 128 threads
    int t = threadIdx.x;
    uint2 raw = *(const uint2*)(g_Hh + (size_t)row * HID + t * 4);
    __half2 h01 = *(__half2*)&raw.x;
    __half2 h23 = *(__half2*)&raw.y;
    float4 sc = *(const float4*)(g_scale + t * 4);
    float4 sh = *(const float4*)(g_shift + t * 4);
    union { __half h4[4]; uint2 u; } H;
    H.h4[0] = __float2half_rn(fmaxf(fmaf(__low2float(h01),  sc.x, sh.x), 0.0f));
    H.h4[1] = __float2half_rn(fmaxf(fmaf(__high2float(h01), sc.y, sh.y), 0.0f));
    H.h4[2] = __float2half_rn(fmaxf(fmaf(__low2float(h23),  sc.z, sh.z), 0.0f));
    H.h4[3] = __float2half_rn(fmaxf(fmaf(__high2float(h23), sc.w, sh.w), 0.0f));
    *(uint2*)(g_XA + (size_t)row * KB2 + IND + t * 4) = H.u;
}

// ---------------- K7: pool finalize over tile partials -----------------------
__global__ void k_poolfin(float* __restrict__ out) {
    int b = blockIdx.y;
    int n = blockIdx.x * 256 + threadIdx.x;
    int t0 = (b * KSEL) / 128;
    int t1 = (b * KSEL + KSEL - 1) / 128;
    float m = -INFINITY;
    for (int t = t0; t <= t1; t++) {
        int bf = (t * 128) / KSEL;
        int seg = (bf == b) ? 0 : 1;
        m = fmaxf(m, g_pmax[(size_t)(t * 2 + seg) * EMB + n]);
    }
    out[b * EMB + n] = m;
}

// ---------------- launch ----------------------------------------------------
extern "C" void kernel_launch(void* const* d_in, const int* in_sizes, int n_in,
                              void* d_out, int out_size) {
    const float* features = (const float*)d_in[0];
    const float* atten    = (const float*)d_in[1];
    const int*   text32   = (const int*)  d_in[2];
    const float* lin_w    = (const float*)d_in[3];
    const float* lin_b    = (const float*)d_in[4];
    const float* w1       = (const float*)d_in[5];
    const float* b1       = (const float*)d_in[6];
    const float* g1       = (const float*)d_in[7];
    const float* be1      = (const float*)d_in[8];
    const float* w2       = (const float*)d_in[9];
    const float* b2       = (const float*)d_in[10];
    float* out = (float*)d_out;

    cudaFuncSetAttribute((const void*)k_mmagemm<0, KB2, IND, 8>,
                         cudaFuncAttributeMaxDynamicSharedMemorySize, GSMEM);
    cudaFuncSetAttribute((const void*)k_mmagemm<1, KB2, KB2, 16>,
                         cudaFuncAttributeMaxDynamicSharedMemorySize, GSMEM);

    __half *w1h, *wb, *xa;
    cudaGetSymbolAddress((void**)&w1h, g_W1h);
    cudaGetSymbolAddress((void**)&wb, g_Wb);
    cudaGetSymbolAddress((void**)&xa, g_XA);

    dim3 tb(32, 8);
    // 1: token lengths
    k_lens  <<<BSZ, 1024>>>(text32);
    // 2-3: Wb transposes (independent; fill slots so scorep lands in slot 4)
    k_prepwb<<<dim3(EMB / 32, IND / 32), tb>>>(lin_w, 0);
    k_prepwb<<<dim3(EMB / 32, HID / 32), tb>>>(w2, IND);
    // 4: partial exp sums, 2 cols/thread float2 loads (ncu-profiled slot)
    k_scorep<<<dim3(SEQ / 512, 4, BSZ), 256>>>(atten);
    // 5: fused scoref + topk (blocks 0-63) + w1 transpose (blocks 64-127)
    k_topk_prepw<<<BSZ + 64, 1024>>>(w1, atten);
    // 6: gather, warp-per-row
    k_gather<<<MR / 8, 256>>>(features);
    // 7: GEMM-A
    k_mmagemm<0, KB2, IND, 8><<<dim3(HID / 128, MT), 256, GSMEM>>>(xa, w1h, b1, nullptr);
    // 8-9
    k_bnfin <<<HID / 256, 256>>>(g1, be1);
    k_act   <<<MR, 128>>>();
    // 10: GEMM-B
    k_mmagemm<1, KB2, KB2, 16><<<dim3(EMB / 128, MT), 256, GSMEM>>>(xa, wb, lin_b, b2);
    // 11: pool finalize
    k_poolfin<<<dim3(EMB / 256, BSZ), 256>>>(out);
}

// round 17
// speedup vs baseline: 1.5731x; 1.5731x over previous
#include <cuda_runtime.h>
#include <cuda_fp16.h>
#include <math.h>
#include <stdint.h>

#define BSZ   64
#define SEQ   1024
#define IND   512
#define EMB   1024
#define HID   512
#define KSEL  306
#define MR    (BSZ*KSEL)     /* 19584 = 153*128 */
#define MT    153            /* m-tiles */
#define KB2   1024           /* GEMM-B K dim */

// ---------------- scratch (device globals: no allocation allowed) -----------
__device__ int   g_len[BSZ];
__device__ int   g_plen[BSZ];
__device__ float g_sps[BSZ*4*SEQ];             /* row-quarter partial exp sums */
__device__ int   g_topk[BSZ*KSEL];
__device__ __half g_XA[(size_t)MR*KB2];        /* [X | A2] packed, stride 1024 */
__device__ __half g_W1h[(size_t)HID*IND];      /* w1^T, stride 512 */
__device__ __half g_Wb[(size_t)EMB*KB2];       /* [lin_w^T | w2^T], stride 1024 */
__device__ __half g_Hh[(size_t)MR*HID];        /* GEMM-A output (pre-BN), fp16 */
__device__ float g_psum[2*MT*HID];
__device__ float g_psq [2*MT*HID];
__device__ float g_scale[HID];
__device__ float g_shift[HID];
__device__ float g_pmax[(size_t)2*MT*EMB];

// ---------------- small PTX helpers -----------------------------------------
__device__ __forceinline__ uint32_t smem_to_u32(const void* p) {
    uint32_t a;
    asm("{ .reg .u64 t; cvta.to.shared.u64 t, %1; cvt.u32.u64 %0, t; }" : "=r"(a) : "l"(p));
    return a;
}
__device__ __forceinline__ void cp_async16(uint32_t saddr, const void* gaddr) {
    asm volatile("cp.async.cg.shared.global [%0], [%1], 16;" :: "r"(saddr), "l"(gaddr));
}
#define CP_COMMIT() asm volatile("cp.async.commit_group;" ::: "memory")
#define CP_WAIT(N)  asm volatile("cp.async.wait_group %0;" :: "n"(N) : "memory")

__device__ __forceinline__ void ldm_x4(uint32_t& r0, uint32_t& r1, uint32_t& r2, uint32_t& r3,
                                       uint32_t addr) {
    asm volatile("ldmatrix.sync.aligned.m8n8.x4.shared.b16 {%0,%1,%2,%3}, [%4];"
                 : "=r"(r0), "=r"(r1), "=r"(r2), "=r"(r3) : "r"(addr));
}
__device__ __forceinline__ void mma16816(float* c, uint32_t a0, uint32_t a1, uint32_t a2,
                                         uint32_t a3, uint32_t b0, uint32_t b1) {
    asm volatile("mma.sync.aligned.m16n8k16.row.col.f32.f16.f16.f32 "
                 "{%0,%1,%2,%3}, {%4,%5,%6,%7}, {%8,%9}, {%0,%1,%2,%3};"
                 : "+f"(c[0]), "+f"(c[1]), "+f"(c[2]), "+f"(c[3])
                 : "r"(a0), "r"(a1), "r"(a2), "r"(a3), "r"(b0), "r"(b1));
}

// fast exp on FMA pipe: exp(x) = 2^(x*log2e)
__device__ __forceinline__ float fexp(float x) {
    float t  = x * 1.44269504088896341f;
    float fi = rintf(t);
    float f  = t - fi;
    float p  = 1.54035303934e-4f;
    p = fmaf(p, f, 1.33335581464e-3f);
    p = fmaf(p, f, 9.61812910763e-3f);
    p = fmaf(p, f, 5.55041086648e-2f);
    p = fmaf(p, f, 2.40226506959e-1f);
    p = fmaf(p, f, 6.93147180560e-1f);
    p = fmaf(p, f, 1.0f);
    return p * __int_as_float(((int)fi + 127) << 23);
}
__device__ __forceinline__ float nfix(float x) {
    if (!isfinite(x)) x = 0.0f;
    return fminf(fmaxf(x, -60.0f), 60.0f);
}

// ---------------- K1: partial exp-sums over row quarters (+inline lens) -----
__global__ void k_scorep(const float* __restrict__ atten, const int* __restrict__ w32) {
    int b = blockIdx.z;
    int q = blockIdx.y;                       // row quarter
    int t = threadIdx.x;                      // 256
    // inline length count (replaces k_lens; ~4KB reads per block)
    int podd = (w32[2 * t + 1] != 0) | (w32[2 * (t + 256) + 1] != 0);
    int oddc = __syncthreads_count(podd);
    int is64 = (oddc == 0);
    int nz = 0;
#pragma unroll
    for (int i = 0; i < 4; i++) {
        int c = t + i * 256;
        if (is64) {
            size_t o = 2 * ((size_t)b * SEQ + c);
            nz += ((w32[o] | w32[o + 1]) != 0);
        } else {
            nz += (w32[(size_t)b * SEQ + c] != 0);
        }
    }
    int len = max(__syncthreads_count(nz > 0) == 0 ? 1 : 0, 1);  // placeholder
    // proper count: sum nz over block
    {
        // warp reduce then smem combine
        int cnt = nz;
#pragma unroll
        for (int o = 16; o > 0; o >>= 1) cnt += __shfl_xor_sync(0xffffffffu, cnt, o);
        __shared__ int sred[8];
        if ((t & 31) == 0) sred[t >> 5] = cnt;
        __syncthreads();
        len = sred[0] + sred[1] + sred[2] + sred[3]
            + sred[4] + sred[5] + sred[6] + sred[7];
        len = max(len, 1);
    }
    if (blockIdx.x == 0 && q == 0 && t == 0) {
        g_len[b] = len;
        g_plen[b] = min(max(len - 2, 1), KSEL);
    }

    int col = blockIdx.x * 256 + t;
    float s = 0.0f;
    if (col > 0 && col < len) {               // col 0 / >=len never needed
        const float* base = atten + (size_t)b * SEQ * SEQ + (size_t)q * 256 * SEQ + col;
        float s0 = 0, s1 = 0, s2 = 0, s3 = 0;
#pragma unroll 2
        for (int r = 0; r < 256; r += 4) {
            float x0 = nfix(base[(size_t)(r + 0) * SEQ]);
            float x1 = nfix(base[(size_t)(r + 1) * SEQ]);
            float x2 = nfix(base[(size_t)(r + 2) * SEQ]);
            float x3 = nfix(base[(size_t)(r + 3) * SEQ]);
            s0 += fexp(x0); s1 += fexp(x1);
            s2 += fexp(x2); s3 += fexp(x3);
        }
        s = (s0 + s1) + (s2 + s3);
    }
    g_sps[((size_t)b * 4 + q) * SEQ + col] = s;
}

// ---------------- K2: fused scoref + top-K sort (blocks<64) | w1^T (rest) ---
__global__ void __launch_bounds__(1024) k_topk_prepw(const float* __restrict__ w1,
                                                     const float* __restrict__ atten) {
    __shared__ unsigned long long key[SEQ];       // 8 KB
    __shared__ float ts[4][32][33];               // transpose wing
    int tid = threadIdx.x;  // 1024
    if (blockIdx.x < BSZ) {
        int b = blockIdx.x;
        int len = g_len[b];
        int eos = len - 1;
        float out;
        if (tid >= len) {
            out = 0.0f;
        } else if (tid == 0 || tid == eos) {
            out = 1.0f / 1024.0f;
        } else {
            const float* sp = g_sps + (size_t)b * 4 * SEQ + tid;
            float s = (sp[0] + sp[SEQ]) + (sp[2 * SEQ] + sp[3 * SEQ]);
            float aeos = nfix(atten[(size_t)b * SEQ * SEQ + (size_t)eos * SEQ + tid]);
            out = fexp(aeos) / s;
        }
        unsigned int vb = __float_as_uint(out);
        key[tid] = ((unsigned long long)vb << 32) | (unsigned int)(SEQ - 1 - tid);
        __syncthreads();
        for (int k = 2; k <= SEQ; k <<= 1) {
            for (int j = k >> 1; j > 0; j >>= 1) {
                int i = tid, ixj = i ^ j;
                if (ixj > i) {
                    bool desc = ((i & k) == 0);
                    unsigned long long a = key[i], c = key[ixj];
                    if (desc ? (a < c) : (a > c)) { key[i] = c; key[ixj] = a; }
                }
                __syncthreads();
            }
        }
        if (tid < KSEL)
            g_topk[b * KSEL + tid] = (SEQ - 1) - (int)(key[tid] & 0xFFFFFFFFu);
    } else {
        int idx = blockIdx.x - BSZ;               // 0..63
        int g  = tid >> 8;                        // tile-in-block 0..3
        int t  = tid & 255;
        int tx = t & 31, ty = t >> 5;             // (32,8)
        int n0 = (idx & 15) * 32;
        int k0 = (idx >> 4) * 128 + g * 32;
#pragma unroll
        for (int i = 0; i < 4; i++) {
            int kl = ty + i * 8;
            ts[g][kl][tx] = w1[(size_t)(k0 + kl) * HID + n0 + tx];
        }
        __syncthreads();
#pragma unroll
        for (int i = 0; i < 4; i++) {
            int nl = ty + i * 8;
            g_W1h[(size_t)(n0 + nl) * IND + k0 + tx] =
                __float2half_rn(ts[g][tx][nl]);
        }
    }
}

// ---------------- K3: gather, warp-per-row (MLP=4, no block sync) ------------
__global__ void __launch_bounds__(256) k_gather(const float* __restrict__ feats) {
    int warp = (blockIdx.x * 8) + (threadIdx.x >> 5);   // row index
    if (warp >= MR) return;
    int lane = threadIdx.x & 31;
    int b   = warp / KSEL;
    int idx = g_topk[warp];
    const float4* src = (const float4*)(feats + ((size_t)b * SEQ + idx) * IND);
    float4 v0 = src[lane];
    float4 v1 = src[lane + 32];
    float4 v2 = src[lane + 64];
    float4 v3 = src[lane + 96];
    float ss = v0.x*v0.x + v0.y*v0.y + v0.z*v0.z + v0.w*v0.w
             + v1.x*v1.x + v1.y*v1.y + v1.z*v1.z + v1.w*v1.w
             + v2.x*v2.x + v2.y*v2.y + v2.z*v2.z + v2.w*v2.w
             + v3.x*v3.x + v3.y*v3.y + v3.z*v3.z + v3.w*v3.w;
#pragma unroll
    for (int o = 16; o > 0; o >>= 1) ss += __shfl_xor_sync(0xffffffffu, ss, o);
    float sc = 1.0f / fmaxf(sqrtf(ss), 1e-6f);
    __half* dst = g_XA + (size_t)warp * KB2;
    union { __half h4[4]; uint2 u; } H;
    float4 vv[4] = {v0, v1, v2, v3};
#pragma unroll
    for (int i = 0; i < 4; i++) {
        H.h4[0] = __float2half_rn(vv[i].x * sc);
        H.h4[1] = __float2half_rn(vv[i].y * sc);
        H.h4[2] = __float2half_rn(vv[i].z * sc);
        H.h4[3] = __float2half_rn(vv[i].w * sc);
        *(uint2*)(dst + (lane + i * 32) * 4) = H.u;
    }
}

// ---------------- K3b: both Wb transposes in one kernel ----------------------
__global__ void k_prepwb(const float* __restrict__ lin_w, const float* __restrict__ w2) {
    __shared__ float s[32][33];
    int n0 = blockIdx.x * 32;
    int yy = blockIdx.y;
    const float* W; int k0, koff;
    if (yy < 32) { W = lin_w; k0 = yy * 32;        koff = 0; }
    else         { W = w2;    k0 = (yy - 32) * 32; koff = IND; }
    int tx = threadIdx.x, ty = threadIdx.y;   // (32,8)
#pragma unroll
    for (int i = 0; i < 4; i++) {
        int kl = ty + i * 8;
        s[kl][tx] = W[(size_t)(k0 + kl) * EMB + n0 + tx];
    }
    __syncthreads();
#pragma unroll
    for (int i = 0; i < 4; i++) {
        int nl = ty + i * 8;
        g_Wb[(size_t)(n0 + nl) * KB2 + koff + k0 + tx] = __float2half_rn(s[tx][nl]);
    }
}

// ---------------- fp16 HMMA GEMM (128x128 tile, BK=64, 3-stage, full unroll) -
#define SKROW 144                /* 64 fp16 = 128 B + 16 pad (ldmatrix conflict-free) */
#define TILEB (128*SKROW)        /* 18432 B */
#define STAGEB (2*TILEB)         /* 36864 B */
#define GSMEM (3*STAGEB)         /* 110592 B, 3 stages */
#define FBS 132                  /* epilogue float buffer row stride */

template <int MODE, int LDA, int LDB, int KTILES>
__global__ void __launch_bounds__(256, 2) k_mmagemm(
    const __half* __restrict__ Ah, const __half* __restrict__ Bh,
    const float* __restrict__ bias0, const float* __restrict__ bias1)
{
    extern __shared__ char smem[];
    const uint32_t sb = smem_to_u32(smem);
    const int tid = threadIdx.x;
    const int lane = tid & 31;
    const int wid  = tid >> 5;
    const int warp_m = wid & 1;        // 2 warps in M
    const int warp_n = wid >> 1;       // 4 warps in N
    const int m0 = blockIdx.y * 128;
    const int n0 = blockIdx.x * 128;

    const int lrow = tid >> 3;         // 0..31
    const int lch  = tid & 7;          // 16B chunk within 128B row

    const __half* gA = Ah + (size_t)(m0 + lrow) * LDA + lch * 8;
    const __half* gB = Bh + (size_t)(n0 + lrow) * LDB + lch * 8;
    const uint32_t sA = sb + lrow * SKROW + lch * 16;
    const uint32_t sB = sb + TILEB + lrow * SKROW + lch * 16;

    auto stage_load = [&](int st, int kt) {
        const uint32_t so = (uint32_t)st * STAGEB;
        const int ko = kt * 64;
#pragma unroll
        for (int it = 0; it < 4; it++) {
            cp_async16(sA + so + it * 32 * SKROW, gA + (size_t)(it * 32) * LDA + ko);
            cp_async16(sB + so + it * 32 * SKROW, gB + (size_t)(it * 32) * LDB + ko);
        }
    };

    stage_load(0, 0); CP_COMMIT();
    stage_load(1, 1); CP_COMMIT();

    float acc[4][4][4];
#pragma unroll
    for (int i = 0; i < 4; i++)
#pragma unroll
        for (int j = 0; j < 4; j++)
#pragma unroll
            for (int c = 0; c < 4; c++) acc[i][j][c] = 0.0f;

    const int lr16 = lane & 15;
    const int lkh  = (lane >> 4) * 16;   // byte offset for k-half
    const uint32_t aAh0 = sb + (warp_m * 64 + lr16) * SKROW + lkh;
    const uint32_t aBh0 = sb + TILEB + (warp_n * 32 + lr16) * SKROW + lkh;

#pragma unroll
    for (int kt = 0; kt < KTILES; kt++) {
        if (kt + 2 < KTILES) {
            CP_WAIT(1);
            __syncthreads();
            stage_load((kt + 2) % 3, kt + 2); CP_COMMIT();
        } else {
            CP_WAIT(0);
            __syncthreads();
        }

        const uint32_t so = (uint32_t)(kt % 3) * STAGEB;   // compile-time after unroll
        const uint32_t aAh = aAh0 + so;
        const uint32_t aBh = aBh0 + so;
#pragma unroll
        for (int kk = 0; kk < 4; kk++) {
            const uint32_t kb = kk * 32;
            uint32_t bh[4][2];
            {
                uint32_t r0, r1, r2, r3;
                ldm_x4(r0, r1, r2, r3, aBh + kb);
                bh[0][0] = r0; bh[0][1] = r2; bh[1][0] = r1; bh[1][1] = r3;
                ldm_x4(r0, r1, r2, r3, aBh + 16 * SKROW + kb);
                bh[2][0] = r0; bh[2][1] = r2; bh[3][0] = r1; bh[3][1] = r3;
            }
#pragma unroll
            for (int mi = 0; mi < 4; mi++) {
                uint32_t a0, a1, a2, a3;
                ldm_x4(a0, a1, a2, a3, aAh + mi * 16 * SKROW + kb);
#pragma unroll
                for (int nj = 0; nj < 4; nj++)
                    mma16816(acc[mi][nj], a0, a1, a2, a3, bh[nj][0], bh[nj][1]);
            }
        }
    }

    // ---------------- epilogue ----------------
    const int rg = lane >> 2;            // row in 8-group
    const int cg = (lane & 3) * 2;       // col pair

    if (MODE == 0) {
        float s[4][2] = {{0,0},{0,0},{0,0},{0,0}};
        float q[4][2] = {{0,0},{0,0},{0,0},{0,0}};
#pragma unroll
        for (int mi = 0; mi < 4; mi++) {
#pragma unroll
            for (int nj = 0; nj < 4; nj++) {
                int m = m0 + warp_m * 64 + mi * 16 + rg;
                int n = n0 + warp_n * 32 + nj * 8 + cg;
                float* c = acc[mi][nj];
                float bv0 = bias0[n];
                float bv1 = bias0[n + 1];
                float2 v01 = make_float2(c[0] + bv0, c[1] + bv1);
                float2 v23 = make_float2(c[2] + bv0, c[3] + bv1);
                *(__half2*)(g_Hh + (size_t)m * HID + n) =
                    __floats2half2_rn(v01.x, v01.y);
                *(__half2*)(g_Hh + (size_t)(m + 8) * HID + n) =
                    __floats2half2_rn(v23.x, v23.y);
                s[nj][0] += v01.x + v23.x;  s[nj][1] += v01.y + v23.y;
                q[nj][0] += v01.x * v01.x + v23.x * v23.x;
                q[nj][1] += v01.y * v01.y + v23.y * v23.y;
            }
        }
#pragma unroll
        for (int o = 4; o <= 16; o <<= 1)
#pragma unroll
            for (int nj = 0; nj < 4; nj++)
#pragma unroll
                for (int p = 0; p < 2; p++) {
                    s[nj][p] += __shfl_xor_sync(0xffffffffu, s[nj][p], o);
                    q[nj][p] += __shfl_xor_sync(0xffffffffu, q[nj][p], o);
                }
        if (rg == 0) {
            int part = blockIdx.y * 2 + warp_m;
            int cbase = n0 + warp_n * 32;
#pragma unroll
            for (int nj = 0; nj < 4; nj++)
#pragma unroll
                for (int p = 0; p < 2; p++) {
                    int cc = cbase + nj * 8 + cg + p;
                    g_psum[part * HID + cc] = s[nj][p];
                    g_psq [part * HID + cc] = q[nj][p];
                }
        }
    } else {
        __syncthreads();                 // all smem reads done; reuse as float buf
        float* fb = (float*)smem;        // 128 x FBS floats
        float* cb = fb + 128 * FBS;      // 4 x 128 combine buffer
#pragma unroll
        for (int mi = 0; mi < 4; mi++) {
#pragma unroll
            for (int nj = 0; nj < 4; nj++) {
                int mrow = warp_m * 64 + mi * 16 + rg;
                int nloc = warp_n * 32 + nj * 8 + cg;
                int n = n0 + nloc;
                float* c = acc[mi][nj];
                float2 b0 = *(const float2*)(bias0 + n);
                float2 b1 = *(const float2*)(bias1 + n);
                float bx = b0.x + b1.x, by = b0.y + b1.y;
                fb[mrow * FBS + nloc]           = c[0] + bx;
                fb[mrow * FBS + nloc + 1]       = c[1] + by;
                fb[(mrow + 8) * FBS + nloc]     = c[2] + bx;
                fb[(mrow + 8) * FBS + nloc + 1] = c[3] + by;
            }
        }
        __syncthreads();
        int col  = tid & 127;
        int half = tid >> 7;
        int b0i  = m0 / KSEL;
        int off0 = m0 - b0i * KSEL;
        int split = min(max((b0i + 1) * KSEL - m0, 0), 128);
        int pl0 = g_plen[b0i];
        int pl1 = (b0i + 1 < BSZ) ? g_plen[b0i + 1] : 0;
        int end0 = min(split, pl0 - off0);
        int end1 = min(128, split + pl1);
        float mx0 = -INFINITY, mx1 = -INFINITY;
        int rbeg = half * 64;
#pragma unroll 4
        for (int r = rbeg; r < rbeg + 64; r++) {
            float v = fb[r * FBS + col];
            if (r < end0) mx0 = fmaxf(mx0, v);
            else if (r >= split && r < end1) mx1 = fmaxf(mx1, v);
        }
        cb[(half * 2 + 0) * 128 + col] = mx0;
        cb[(half * 2 + 1) * 128 + col] = mx1;
        __syncthreads();
        if (tid < 128) {
            float a0 = fmaxf(cb[0 * 128 + tid], cb[2 * 128 + tid]);
            float a1 = fmaxf(cb[1 * 128 + tid], cb[3 * 128 + tid]);
            g_pmax[(size_t)(blockIdx.y * 2 + 0) * EMB + n0 + tid] = a0;
            g_pmax[(size_t)(blockIdx.y * 2 + 1) * EMB + n0 + tid] = a1;
        }
    }
}

// ---------------- K5b: BN finalize -------------------------------------------
__global__ void k_bnfin(const float* __restrict__ g1, const float* __restrict__ be1) {
    int c = blockIdx.x * 256 + threadIdx.x;   // 512 cols
    float s = 0, q = 0;
    for (int p = 0; p < 2 * MT; p++) { s += g_psum[p * HID + c]; q += g_psq[p * HID + c]; }
    const float invN = 1.0f / (float)MR;
    float mu  = s * invN;
    float var = q * invN - mu * mu;
    float inv = 1.0f / sqrtf(var + 1e-5f);
    float sc  = g1[c] * inv;
    g_scale[c] = sc;
    g_shift[c] = be1[c] - mu * sc;
}

// ---------------- K5c: A2 = relu(BN(h)) -> fp16 into g_XA[:,512:1024] --------
__global__ void k_act() {
    int row = blockIdx.x;            // MR blocks, 128 threads
    int t = threadIdx.x;
    uint2 raw = *(const uint2*)(g_Hh + (size_t)row * HID + t * 4);
    __half2 h01 = *(__half2*)&raw.x;
    __half2 h23 = *(__half2*)&raw.y;
    float4 sc = *(const float4*)(g_scale + t * 4);
    float4 sh = *(const float4*)(g_shift + t * 4);
    union { __half h4[4]; uint2 u; } H;
    H.h4[0] = __float2half_rn(fmaxf(fmaf(__low2float(h01),  sc.x, sh.x), 0.0f));
    H.h4[1] = __float2half_rn(fmaxf(fmaf(__high2float(h01), sc.y, sh.y), 0.0f));
    H.h4[2] = __float2half_rn(fmaxf(fmaf(__low2float(h23),  sc.z, sh.z), 0.0f));
    H.h4[3] = __float2half_rn(fmaxf(fmaf(__high2float(h23), sc.w, sh.w), 0.0f));
    *(uint2*)(g_XA + (size_t)row * KB2 + IND + t * 4) = H.u;
}

// ---------------- K7: pool finalize over tile partials -----------------------
__global__ void k_poolfin(float* __restrict__ out) {
    int b = blockIdx.y;
    int n = blockIdx.x * 256 + threadIdx.x;
    int t0 = (b * KSEL) / 128;
    int t1 = (b * KSEL + KSEL - 1) / 128;
    float m = -INFINITY;
    for (int t = t0; t <= t1; t++) {
        int bf = (t * 128) / KSEL;
        int seg = (bf == b) ? 0 : 1;
        m = fmaxf(m, g_pmax[(size_t)(t * 2 + seg) * EMB + n]);
    }
    out[b * EMB + n] = m;
}

// ---------------- launch ----------------------------------------------------
extern "C" void kernel_launch(void* const* d_in, const int* in_sizes, int n_in,
                              void* d_out, int out_size) {
    const float* features = (const float*)d_in[0];
    const float* atten    = (const float*)d_in[1];
    const int*   text32   = (const int*)  d_in[2];
    const float* lin_w    = (const float*)d_in[3];
    const float* lin_b    = (const float*)d_in[4];
    const float* w1       = (const float*)d_in[5];
    const float* b1       = (const float*)d_in[6];
    const float* g1       = (const float*)d_in[7];
    const float* be1      = (const float*)d_in[8];
    const float* w2       = (const float*)d_in[9];
    const float* b2       = (const float*)d_in[10];
    float* out = (float*)d_out;

    cudaFuncSetAttribute((const void*)k_mmagemm<0, KB2, IND, 8>,
                         cudaFuncAttributeMaxDynamicSharedMemorySize, GSMEM);
    cudaFuncSetAttribute((const void*)k_mmagemm<1, KB2, KB2, 16>,
                         cudaFuncAttributeMaxDynamicSharedMemorySize, GSMEM);

    __half *w1h, *wb, *xa;
    cudaGetSymbolAddress((void**)&w1h, g_W1h);
    cudaGetSymbolAddress((void**)&wb, g_Wb);
    cudaGetSymbolAddress((void**)&xa, g_XA);

    // 1: partial exp sums (lens computed inline; block x=0,q=0 publishes)
    k_scorep<<<dim3(SEQ / 256, 4, BSZ), 256>>>(atten, text32);
    // 2: fused scoref + topk (blocks 0-63) + w1 transpose (blocks 64-127)
    k_topk_prepw<<<BSZ + 64, 1024>>>(w1, atten);
    // 3: gather, warp-per-row
    k_gather<<<MR / 8, 256>>>(features);
    // 4: GEMM-A
    k_mmagemm<0, KB2, IND, 8><<<dim3(HID / 128, MT), 256, GSMEM>>>(xa, w1h, b1, nullptr);
    // 5: both Wb transposes in one launch
    k_prepwb<<<dim3(EMB / 32, 48), dim3(32, 8)>>>(lin_w, w2);
    // 6-8
    k_bnfin <<<HID / 256, 256>>>(g1, be1);
    k_act   <<<MR, 128>>>();
    k_mmagemm<1, KB2, KB2, 16><<<dim3(EMB / 128, MT), 256, GSMEM>>>(xa, wb, lin_b, b2);
    // 9: pool finalize
    k_poolfin<<<dim3(EMB / 256, BSZ), 256>>>(out);
}